// round 10
// baseline (speedup 1.0000x reference)
#include <cuda_runtime.h>
#include <cstdint>

// Problem dims (fixed)
#define B_ 128
#define C_ 16
#define F_ 128
#define D_ 512

// Scratch (no allocation allowed)
__device__ float g_xnT[512 * 2048];          // normalized c_feats, transposed [k][m]
__device__ float g_ffD[128 * 512 * 256];     // f_feats transposed+DUPLICATED per n: [n][k][2f]
__device__ float g_rnc[2048];                // 1/||c_feats row||
__device__ float g_rnf[128 * 128];           // 1/||f_feats[n,f]||

// ---------------------------------------------------------------------------
// Kernel A: reciprocal row norms for both tensors.
// ---------------------------------------------------------------------------
__global__ void prep_norms(const float* __restrict__ cf, const float* __restrict__ ff) {
    int row = blockIdx.x;
    int t = threadIdx.x;  // 128 threads, one float4 each
    const float* src = (row < 2048) ? (cf + (size_t)row * D_)
                                    : (ff + (size_t)(row - 2048) * D_);
    float4 v = ((const float4*)src)[t];
    float ss = v.x * v.x + v.y * v.y + v.z * v.z + v.w * v.w;
#pragma unroll
    for (int o = 16; o > 0; o >>= 1) ss += __shfl_xor_sync(0xffffffffu, ss, o);
    __shared__ float sred[4];
    if ((t & 31) == 0) sred[t >> 5] = ss;
    __syncthreads();
    if (t == 0) {
        float nrm = sqrtf(sred[0] + sred[1] + sred[2] + sred[3]);
        if (row < 2048) g_rnc[row] = 1.0f / nrm;
        else            g_rnf[row - 2048] = 1.0f / nrm;
    }
}

// ---------------------------------------------------------------------------
// Kernel B1: transpose + normalize c_feats -> g_xnT [512][2048]
// ---------------------------------------------------------------------------
__global__ void transpose_c(const float* __restrict__ cf) {
    __shared__ float t[32][33];
    int kbase = blockIdx.x * 32, mbase = blockIdx.y * 32;
    int tx = threadIdx.x, ty = threadIdx.y;
#pragma unroll
    for (int i = 0; i < 4; i++) {
        int m = mbase + ty + i * 8;
        t[ty + i * 8][tx] = cf[(size_t)m * D_ + kbase + tx] * g_rnc[m];
    }
    __syncthreads();
#pragma unroll
    for (int i = 0; i < 4; i++) {
        g_xnT[(size_t)(kbase + ty + i * 8) * 2048 + mbase + tx] = t[tx][ty + i * 8];
    }
}

// ---------------------------------------------------------------------------
// Kernel B2: transpose f_feats per n, writing each value DUPLICATED:
// g_ffD[n][k][2f] = g_ffD[n][k][2f+1] = ff[n][f][k].
// grid (16, 4, 128), block (32, 8)
// ---------------------------------------------------------------------------
__global__ void transpose_f(const float* __restrict__ ff) {
    __shared__ float t[32][33];
    int kbase = blockIdx.x * 32, fbase = blockIdx.y * 32, n = blockIdx.z;
    int tx = threadIdx.x, ty = threadIdx.y;
    const float* fin = ff + (size_t)n * F_ * D_;
    float* fout = g_ffD + (size_t)n * D_ * 256;
#pragma unroll
    for (int i = 0; i < 4; i++) {
        t[ty + i * 8][tx] = fin[(size_t)(fbase + ty + i * 8) * D_ + kbase + tx];
    }
    __syncthreads();
#pragma unroll
    for (int i = 0; i < 4; i++) {
        float v = t[tx][ty + i * 8];
        float2 d; d.x = v; d.y = v;
        *(float2*)(fout + (size_t)(kbase + ty + i * 8) * 256 + 2 * (fbase + tx)) = d;
    }
}

// ---------------------------------------------------------------------------
// Packed dual-lane fp32 FMA — bit-exact vs two scalar FFMA.rn.
// ---------------------------------------------------------------------------
__device__ __forceinline__ void fma2(unsigned long long& d, unsigned long long a,
                                     unsigned long long b) {
    asm("fma.rn.f32x2 %0, %1, %2, %0;" : "+l"(d) : "l"(a), "l"(b));
}

__device__ __forceinline__ void cp_async16(float* sp, const float* gp) {
    unsigned sa = (unsigned)__cvta_generic_to_shared(sp);
    asm volatile("cp.async.cg.shared.global [%0], [%1], 16;\n" ::"r"(sa), "l"(gp));
}

// ---------------------------------------------------------------------------
// Kernel C: GEMM (3-stage cp.async, MOV-free f32x2 row-pair packing) + DTW
// Grid: (n=128, mblk=16). Block 256 threads = 8 warps; warp w owns pair
// (m = mblk*8 + w, n).
//
// Smem layout (union):
//   [0, 73728)   3 stage buffers, 24 KB each: As 16x128 f32 | Bs 16x256 f32(dup)
//   [0, 65536)   S[128][128] (aliases stages; live only after mainloop)
//   [73728, 77824)  mvb: 8 warps x 512 B of 2-bit moves
//   [77824, 77888)  rnf_s[16]
// ---------------------------------------------------------------------------
static constexpr int STG_SZ = 24576;
static constexpr int MVB_OFF = 73728;
static constexpr int RNF_OFF = 77824;
static constexpr int SMEM_TOTAL = 77888;

__global__ void __launch_bounds__(256, 2)
dtw_kernel(float* __restrict__ out) {
    extern __shared__ char smem[];
    float* Sf = (float*)smem;
    float* rnf_s = (float*)(smem + RNF_OFF);

    const int tid = threadIdx.x;
    const int n = blockIdx.x, mblk = blockIdx.y;
    const int tr = tid >> 4, tc = tid & 15;

    if (tid < 16) rnf_s[tid] = g_rnf[n * F_ + tid];

    const float* An = g_xnT + mblk * 128;              // + k*2048 + m
    const float* Bn = g_ffD + (size_t)n * D_ * 256;    // + k*256 + 2f (dup)

    // stage tile kt into stage buffer s: A 512 + B 1024 16B chunks, 6/thread
    auto stage = [&](int s, int kt) {
        float* As = (float*)(smem + s * STG_SZ);        // 16 x 128 floats
        float* Bs = As + 2048;                           // 16 x 256 floats (dup)
        const int kbase = kt * 16;
#pragma unroll
        for (int i = 0; i < 2; i++) {
            int idx = tid + i * 256;
            int r = idx >> 5, seg = idx & 31;
            cp_async16(As + r * 128 + seg * 4,
                       An + (size_t)(kbase + r) * 2048 + seg * 4);
        }
#pragma unroll
        for (int i = 0; i < 4; i++) {
            int idx = tid + i * 256;
            int r = idx >> 6, seg = idx & 63;
            cp_async16(Bs + r * 256 + seg * 4,
                       Bn + (size_t)(kbase + r) * 256 + seg * 4);
        }
        asm volatile("cp.async.commit_group;\n" ::);
    };

    // acc2[p][j]: rows (tr*8+2p, +1), col f = 32*(j>>1) + 2*tc + (j&1)
    unsigned long long acc2[4][8];
#pragma unroll
    for (int p = 0; p < 4; p++)
#pragma unroll
        for (int j = 0; j < 8; j++) acc2[p][j] = 0ull;

    stage(0, 0);
    stage(1, 1);

    int s = 0;
    for (int kt = 0; kt < 32; kt++) {
        if (kt == 31) asm volatile("cp.async.wait_group 0;\n" ::);
        else          asm volatile("cp.async.wait_group 1;\n" ::);
        __syncthreads();
        if (kt < 30) {
            int s2 = s + 2; if (s2 >= 3) s2 -= 3;
            stage(s2, kt + 2);
        }
        const float* As = (const float*)(smem + s * STG_SZ);
        const float* Bs = As + 2048;
#pragma unroll
        for (int k = 0; k < 16; k++) {
            // A: 2 x LDS.128 -> 4 packed row-pair operands (no MOV)
            ulonglong2 aA = *(const ulonglong2*)&As[k * 128 + tr * 8];
            ulonglong2 aB = *(const ulonglong2*)&As[k * 128 + tr * 8 + 4];
            unsigned long long ap[4] = {aA.x, aA.y, aB.x, aB.y};
            // B: 4 x LDS.128 from dup rows -> 8 packed {b,b} operands (no MOV)
            unsigned long long bp[8];
#pragma unroll
            for (int L = 0; L < 4; L++) {
                ulonglong2 bv = *(const ulonglong2*)&Bs[k * 256 + L * 64 + tc * 4];
                bp[L * 2 + 0] = bv.x;
                bp[L * 2 + 1] = bv.y;
            }
#pragma unroll
            for (int p = 0; p < 4; p++)
#pragma unroll
                for (int j = 0; j < 8; j++)
                    fma2(acc2[p][j], ap[p], bp[j]);
        }
        s = (s + 1 == 3) ? 0 : s + 1;
    }
    __syncthreads();  // stage buffers dead -> S may be written

    // Epilogue: unpack (row-pair, col) accs, rescale (f<=c), store S.
    // Warp's rows stay inside its own 16-row slab (tr in {2w,2w+1}).
#pragma unroll
    for (int p = 0; p < 4; p++) {
        int r0 = tr * 8 + 2 * p;      // low lane row
        int c0 = r0 & 15, c1 = (r0 + 1) & 15;
#pragma unroll
        for (int j = 0; j < 8; j++) {
            float lo, hi;
            asm("mov.b64 {%0, %1}, %2;" : "=f"(lo), "=f"(hi) : "l"(acc2[p][j]));
            int f = 32 * (j >> 1) + 2 * tc + (j & 1);
            if (f <= c0) lo *= rnf_s[f];
            if (f <= c1) hi *= rnf_s[f];
            Sf[r0 * 128 + f] = lo;
            Sf[(r0 + 1) * 128 + f] = hi;
        }
    }
    __syncwarp();

    // ---- DTW DP (reference's row-parallel form), one warp per pair ----
    const int w = tid >> 5, lane = tid & 31;
    const float NEG = __int_as_float(0xff800000);  // -inf
    float Rp[4] = {NEG, NEG, NEG, NEG};            // D[i-1] at my 4 cols
    float p_prev = 0.0f;                            // padded col-0 of prev row
    float* Srows = Sf + w * 16 * 128;
    unsigned char* mvb = (unsigned char*)(smem + MVB_OFF) + w * 512;

    for (int i = 1; i <= 16; i++) {
        float4 sv = *(const float4*)&Srows[(i - 1) * 128 + lane * 4];
        // local inclusive cumsum
        float cl0 = sv.x, cl1 = cl0 + sv.y, cl2 = cl1 + sv.z, cl3 = cl2 + sv.w;
        float inc = cl3;
#pragma unroll
        for (int d = 1; d < 32; d <<= 1) {
            float tsh = __shfl_up_sync(0xffffffffu, inc, d);
            if (lane >= d) inc += tsh;
        }
        float ex = __shfl_up_sync(0xffffffffu, inc, 1);
        if (lane == 0) ex = 0.0f;
        float Cc0 = ex + cl0, Cc1 = ex + cl1, Cc2 = ex + cl2, Cc3 = ex + cl3;
        // A[j] = max(D[i-1,j], D[i-1,j-1])
        float rp_left = __shfl_up_sync(0xffffffffu, Rp[3], 1);
        if (lane == 0) rp_left = p_prev;
        float A0 = fmaxf(Rp[0], rp_left);
        float A1 = fmaxf(Rp[1], Rp[0]);
        float A2 = fmaxf(Rp[2], Rp[1]);
        float A3 = fmaxf(Rp[3], Rp[2]);
        // T = A - Cm1, local cummax
        float M0 = A0 - ex;
        float M1 = fmaxf(M0, A1 - Cc0);
        float M2 = fmaxf(M1, A2 - Cc1);
        float M3 = fmaxf(M2, A3 - Cc2);
        float mscan = M3;
#pragma unroll
        for (int d = 1; d < 32; d <<= 1) {
            float tsh = __shfl_up_sync(0xffffffffu, mscan, d);
            if (lane >= d) mscan = fmaxf(mscan, tsh);
        }
        float exm = __shfl_up_sync(0xffffffffu, mscan, 1);
        if (lane == 0) exm = NEG;
        float Rc[4];
        Rc[0] = Cc0 + fmaxf(M0, exm);
        Rc[1] = Cc1 + fmaxf(M1, exm);
        Rc[2] = Cc2 + fmaxf(M2, exm);
        Rc[3] = Cc3 + fmaxf(M3, exm);
        // mv = argmax(up, left, diag), first-max priority (matches jnp.argmax)
        float rc_left = __shfl_up_sync(0xffffffffu, Rc[3], 1);
        if (lane == 0) rc_left = NEG;  // padded col-0 of current row
        unsigned int byte = 0;
#pragma unroll
        for (int u = 0; u < 4; u++) {
            float up = Rp[u];
            float left = (u == 0) ? rc_left : Rc[u - 1];
            float dg = (u == 0) ? rp_left : Rp[u - 1];
            int m;
            if (up >= left && up >= dg) m = 0;
            else if (left >= dg) m = 1;
            else m = 2;
            byte |= (unsigned)m << (2 * u);
        }
        mvb[(i - 1) * 32 + lane] = (unsigned char)byte;
        Rp[0] = Rc[0]; Rp[1] = Rc[1]; Rp[2] = Rc[2]; Rp[3] = Rc[3];
        p_prev = NEG;
    }
    __syncwarp();

    // Zero mask (reuse S slab), then lane 0 backtracks writing 1.0
    float4* mreg = (float4*)Srows;
    for (int t2 = lane; t2 < 512; t2 += 32) mreg[t2] = make_float4(0.f, 0.f, 0.f, 0.f);
    __syncwarp();
    if (lane == 0) {
        int i = 16, j = 128;
        while (i > 0 && j > 0) {
            Srows[(i - 1) * 128 + (j - 1)] = 1.0f;
            unsigned int byte = mvb[(i - 1) * 32 + ((j - 1) >> 2)];
            int m = (byte >> (2 * ((j - 1) & 3))) & 3;
            if (m == 0) i -= 1;
            else if (m == 1) j -= 1;
            else { i -= 1; j -= 1; }
        }
    }
    __syncwarp();

    // Coalesced store: out[m][n][c][f]
    int mglob = mblk * 8 + w;
    float* outp = out + (((size_t)mglob * 128 + n) * 16) * 128;
    const float4* srcp = (const float4*)Srows;
    float4* dstp = (float4*)outp;
    for (int t2 = lane; t2 < 512; t2 += 32) dstp[t2] = srcp[t2];
}

// ---------------------------------------------------------------------------
extern "C" void kernel_launch(void* const* d_in, const int* in_sizes, int n_in,
                              void* d_out, int out_size) {
    const float* cf = (const float*)d_in[0];  // c_feats [128,16,512]
    const float* ff = (const float*)d_in[1];  // f_feats [128,128,512]
    float* out = (float*)d_out;               // [128,128,16,128] float32

    prep_norms<<<18432, 128>>>(cf, ff);
    {
        dim3 g(16, 64), b(32, 8);
        transpose_c<<<g, b>>>(cf);
    }
    {
        dim3 g(16, 4, 128), b(32, 8);
        transpose_f<<<g, b>>>(ff);
    }

    cudaFuncSetAttribute(dtw_kernel, cudaFuncAttributeMaxDynamicSharedMemorySize,
                         SMEM_TOTAL);
    dim3 grid(128, 16);
    dtw_kernel<<<grid, 256, SMEM_TOTAL>>>(out);
}